// round 7
// baseline (speedup 1.0000x reference)
#include <cuda_runtime.h>
#include <cstdint>

// Attention (B,H,S,D)=(256,32,16,64): qk^T/sqrt(8)+1, softmax, JAX threefry
// dropout (key 42, keep 0.7, partitionable XOR-fold), @V.
// One warp per head, cp.async staging, 4x2 tile, two-pass AV (reg-lean).

#define TPB   64
#define WPB   2                 // warps (=heads) per CTA
#define NBLK  (8192 / WPB)
#define QKSTR 17                // q/k smem row stride (float4)
#define ASTR  24                // attn smem row stride (floats)

#define TF_ROUND(r) { x0 += x1; x1 = __funnelshift_l(x1, x1, (r)); x1 ^= x0; }

static __device__ __forceinline__ uint32_t jax_threefry_bits(uint32_t idx) {
    const uint32_t k0 = 0u, k1 = 42u, k2 = 0u ^ 42u ^ 0x1BD11BDAu;
    uint32_t x0 = 0u + k0;
    uint32_t x1 = idx + k1;
    TF_ROUND(13) TF_ROUND(15) TF_ROUND(26) TF_ROUND(6)
    x0 += k1; x1 += k2 + 1u;
    TF_ROUND(17) TF_ROUND(29) TF_ROUND(16) TF_ROUND(24)
    x0 += k2; x1 += k0 + 2u;
    TF_ROUND(13) TF_ROUND(15) TF_ROUND(26) TF_ROUND(6)
    x0 += k0; x1 += k1 + 3u;
    TF_ROUND(17) TF_ROUND(29) TF_ROUND(16) TF_ROUND(24)
    x0 += k1; x1 += k2 + 4u;
    TF_ROUND(13) TF_ROUND(15) TF_ROUND(26) TF_ROUND(6)
    x0 += k2; x1 += k0 + 5u;
    return x0 ^ x1;             // partitionable mode XOR fold
}

static __device__ __forceinline__ float drop_scale(uint32_t idx) {
    uint32_t bits = jax_threefry_bits(idx);
    float u = __uint_as_float((bits >> 9) | 0x3f800000u) - 1.0f;
    return (u < 0.7f) ? (1.0f / 0.7f) : 0.0f;
}

static __device__ __forceinline__ float dot4(float4 a, float4 b) {
    return a.x * b.x + a.y * b.y + a.z * b.z + a.w * b.w;
}

static __device__ __forceinline__ void cp_async16(void* smem_dst, const void* gsrc) {
    uint32_t s = (uint32_t)__cvta_generic_to_shared(smem_dst);
    asm volatile("cp.async.cg.shared.global [%0], [%1], 16;\n"
                 :: "r"(s), "l"(gsrc) : "memory");
}

__global__ __launch_bounds__(TPB, 12) void attn_drop_kernel(
    const float4* __restrict__ qg,
    const float4* __restrict__ kg,
    const float4* __restrict__ vg,
    float4* __restrict__ og)
{
    __shared__ float4 sq[WPB][16 * QKSTR];
    __shared__ float4 sk[WPB][16 * QKSTR];
    __shared__ float4 sv[WPB][256];
    __shared__ float  sattn[WPB][16 * ASTR];

    const int w    = threadIdx.x >> 5;
    const int lane = threadIdx.x & 31;
    const int bh   = blockIdx.x * WPB + w;
    const int base = bh << 8;            // float4 offset of this head
    const int rg   = lane >> 3;          // rows rg, rg+4, rg+8, rg+12
    const int c2   = lane & 7;           // cols c2, c2+8

    // ---- stage this head's q,k,v via cp.async ----
    #pragma unroll
    for (int it = 0; it < 8; ++it) {
        int idx = lane + 32 * it;
        int r = idx >> 4, c = idx & 15;
        cp_async16(&sq[w][r * QKSTR + c], &qg[base + idx]);
        cp_async16(&sk[w][r * QKSTR + c], &kg[base + idx]);
        cp_async16(&sv[w][idx],           &vg[base + idx]);
    }
    asm volatile("cp.async.commit_group;\n" ::: "memory");
    asm volatile("cp.async.wait_group 0;\n" ::: "memory");
    __syncwarp();

    // ---- scores: rows rg+4j (j=0..3), cols c2 & c2+8 ----
    float s[4][2] = {{0,0},{0,0},{0,0},{0,0}};
    #pragma unroll
    for (int i = 0; i < 16; ++i) {
        float4 b0 = sk[w][c2 * QKSTR + i];
        float4 b1 = sk[w][(c2 + 8) * QKSTR + i];
        #pragma unroll
        for (int j = 0; j < 4; ++j) {
            float4 a = sq[w][(rg + 4 * j) * QKSTR + i];
            s[j][0] += dot4(a, b0);
            s[j][1] += dot4(a, b1);
        }
    }

    const float SCALE = 0.35355339059327373f;
    #pragma unroll
    for (int j = 0; j < 4; ++j) {
        int row = rg + 4 * j;
        float s0 = s[j][0] * SCALE + 1.0f;
        float s1 = s[j][1] * SCALE + 1.0f;
        float m = fmaxf(s0, s1);
        #pragma unroll
        for (int o = 4; o; o >>= 1)
            m = fmaxf(m, __shfl_xor_sync(0xffffffffu, m, o, 8));
        float e0 = __expf(s0 - m), e1 = __expf(s1 - m);
        float t = e0 + e1;
        #pragma unroll
        for (int o = 4; o; o >>= 1)
            t += __shfl_xor_sync(0xffffffffu, t, o, 8);
        float inv = 1.0f / t;
        uint32_t ib = (uint32_t)(base + row * 16 + c2);
        sattn[w][row * ASTR + c2]     = e0 * inv * drop_scale(ib);
        sattn[w][row * ASTR + c2 + 8] = e1 * inv * drop_scale(ib + 8u);
    }
    __syncwarp();

    // ---- AV: two column passes (reg-lean) ----
    #pragma unroll
    for (int half = 0; half < 2; ++half) {
        const int cc = c2 + 8 * half;
        float4 acc[4];
        #pragma unroll
        for (int j = 0; j < 4; ++j) acc[j] = make_float4(0, 0, 0, 0);

        #pragma unroll
        for (int uc = 0; uc < 4; ++uc) {
            float4 a4[4];
            #pragma unroll
            for (int j = 0; j < 4; ++j)
                a4[j] = *(const float4*)&sattn[w][(rg + 4 * j) * ASTR + 4 * uc];
            #pragma unroll
            for (int t = 0; t < 4; ++t) {
                float4 v0 = sv[w][(4 * uc + t) * 16 + cc];
                #pragma unroll
                for (int j = 0; j < 4; ++j) {
                    float a = (t == 0) ? a4[j].x : (t == 1) ? a4[j].y
                            : (t == 2) ? a4[j].z : a4[j].w;
                    acc[j].x += a * v0.x; acc[j].y += a * v0.y;
                    acc[j].z += a * v0.z; acc[j].w += a * v0.w;
                }
            }
        }
        #pragma unroll
        for (int j = 0; j < 4; ++j)
            og[base + (rg + 4 * j) * 16 + cc] = acc[j];
    }
}

extern "C" void kernel_launch(void* const* d_in, const int* in_sizes, int n_in,
                              void* d_out, int out_size) {
    attn_drop_kernel<<<NBLK, TPB>>>(
        (const float4*)d_in[0],   // q
        (const float4*)d_in[1],   // k
        (const float4*)d_in[2],   // v
        (float4*)d_out);
}

// round 8
// speedup vs baseline: 1.1445x; 1.1445x over previous
#include <cuda_runtime.h>
#include <cstdint>

// Attention (B,H,S,D)=(256,32,16,64): qk^T/sqrt(8)+1, softmax, JAX threefry
// dropout (key 42, keep 0.7, partitionable XOR-fold), @V.
// Warp-per-head, cp.async (split groups), threefry hoisted into DRAM bubble,
// 4x2 tile, one-pass AV.

#define TPB   64
#define WPB   2                 // warps (=heads) per CTA
#define NBLK  (8192 / WPB)
#define QKSTR 17                // q/k smem row stride (float4)
#define ASTR  24                // attn smem row stride (floats)

#define TF_ROUND(r) { x0 += x1; x1 = __funnelshift_l(x1, x1, (r)); x1 ^= x0; }

static __device__ __forceinline__ uint32_t jax_threefry_bits(uint32_t idx) {
    const uint32_t k0 = 0u, k1 = 42u, k2 = 0u ^ 42u ^ 0x1BD11BDAu;
    uint32_t x0 = 0u + k0;
    uint32_t x1 = idx + k1;
    TF_ROUND(13) TF_ROUND(15) TF_ROUND(26) TF_ROUND(6)
    x0 += k1; x1 += k2 + 1u;
    TF_ROUND(17) TF_ROUND(29) TF_ROUND(16) TF_ROUND(24)
    x0 += k2; x1 += k0 + 2u;
    TF_ROUND(13) TF_ROUND(15) TF_ROUND(26) TF_ROUND(6)
    x0 += k0; x1 += k1 + 3u;
    TF_ROUND(17) TF_ROUND(29) TF_ROUND(16) TF_ROUND(24)
    x0 += k1; x1 += k2 + 4u;
    TF_ROUND(13) TF_ROUND(15) TF_ROUND(26) TF_ROUND(6)
    x0 += k2; x1 += k0 + 5u;
    return x0 ^ x1;             // partitionable mode XOR fold
}

static __device__ __forceinline__ float drop_scale(uint32_t idx) {
    uint32_t bits = jax_threefry_bits(idx);
    float u = __uint_as_float((bits >> 9) | 0x3f800000u) - 1.0f;
    return (u < 0.7f) ? (1.0f / 0.7f) : 0.0f;
}

static __device__ __forceinline__ float dot4(float4 a, float4 b) {
    return a.x * b.x + a.y * b.y + a.z * b.z + a.w * b.w;
}

static __device__ __forceinline__ void cp_async16(void* smem_dst, const void* gsrc) {
    uint32_t s = (uint32_t)__cvta_generic_to_shared(smem_dst);
    asm volatile("cp.async.cg.shared.global [%0], [%1], 16;\n"
                 :: "r"(s), "l"(gsrc) : "memory");
}

__global__ __launch_bounds__(TPB, 7) void attn_drop_kernel(
    const float4* __restrict__ qg,
    const float4* __restrict__ kg,
    const float4* __restrict__ vg,
    float4* __restrict__ og)
{
    __shared__ float4 sq[WPB][16 * QKSTR];
    __shared__ float4 sk[WPB][16 * QKSTR];
    __shared__ float4 sv[WPB][256];
    __shared__ float  sattn[WPB][16 * ASTR];

    const int w    = threadIdx.x >> 5;
    const int lane = threadIdx.x & 31;
    const int bh   = blockIdx.x * WPB + w;
    const int base = bh << 8;            // float4 offset of this head
    const int rg   = lane >> 3;          // rows rg, rg+4, rg+8, rg+12
    const int c2   = lane & 7;           // cols c2, c2+8

    // ---- group 0: k + q (needed for scores) ----
    #pragma unroll
    for (int it = 0; it < 8; ++it) {
        int idx = lane + 32 * it;
        int r = idx >> 4, c = idx & 15;
        cp_async16(&sk[w][r * QKSTR + c], &kg[base + idx]);
        cp_async16(&sq[w][r * QKSTR + c], &qg[base + idx]);
    }
    asm volatile("cp.async.commit_group;\n" ::: "memory");
    // ---- group 1: v (needed only for AV) ----
    #pragma unroll
    for (int it = 0; it < 8; ++it) {
        int idx = lane + 32 * it;
        cp_async16(&sv[w][idx], &vg[base + idx]);
    }
    asm volatile("cp.async.commit_group;\n" ::: "memory");

    // ---- threefry dropout scales: index-only, fill the DRAM bubble ----
    float drop[4][2];
    #pragma unroll
    for (int j = 0; j < 4; ++j) {
        uint32_t ib = (uint32_t)(base + (rg + 4 * j) * 16 + c2);
        drop[j][0] = drop_scale(ib);
        drop[j][1] = drop_scale(ib + 8u);
    }

    // wait for k+q (v may still be in flight)
    asm volatile("cp.async.wait_group 1;\n" ::: "memory");
    __syncwarp();

    // ---- scores: rows rg+4j (j=0..3), cols c2 & c2+8 ----
    float s[4][2] = {{0,0},{0,0},{0,0},{0,0}};
    #pragma unroll
    for (int i = 0; i < 16; ++i) {
        float4 b0 = sk[w][c2 * QKSTR + i];
        float4 b1 = sk[w][(c2 + 8) * QKSTR + i];
        #pragma unroll
        for (int j = 0; j < 4; ++j) {
            float4 a = sq[w][(rg + 4 * j) * QKSTR + i];
            s[j][0] += dot4(a, b0);
            s[j][1] += dot4(a, b1);
        }
    }

    const float SCALE = 0.35355339059327373f;
    #pragma unroll
    for (int j = 0; j < 4; ++j) {
        int row = rg + 4 * j;
        float s0 = s[j][0] * SCALE + 1.0f;
        float s1 = s[j][1] * SCALE + 1.0f;
        float m = fmaxf(s0, s1);
        #pragma unroll
        for (int o = 4; o; o >>= 1)
            m = fmaxf(m, __shfl_xor_sync(0xffffffffu, m, o, 8));
        float e0 = __expf(s0 - m), e1 = __expf(s1 - m);
        float t = e0 + e1;
        #pragma unroll
        for (int o = 4; o; o >>= 1)
            t += __shfl_xor_sync(0xffffffffu, t, o, 8);
        float inv = __fdividef(1.0f, t);
        sattn[w][row * ASTR + c2]     = e0 * inv * drop[j][0];
        sattn[w][row * ASTR + c2 + 8] = e1 * inv * drop[j][1];
    }

    // wait for v, then warp-local handoff of sattn + sv
    asm volatile("cp.async.wait_group 0;\n" ::: "memory");
    __syncwarp();

    // ---- AV: one pass, rows rg+4j x col4s c2, c2+8 ----
    float4 acc[4][2];
    #pragma unroll
    for (int j = 0; j < 4; ++j) {
        acc[j][0] = make_float4(0, 0, 0, 0);
        acc[j][1] = make_float4(0, 0, 0, 0);
    }

    #pragma unroll
    for (int uc = 0; uc < 4; ++uc) {
        float4 a4[4];
        #pragma unroll
        for (int j = 0; j < 4; ++j)
            a4[j] = *(const float4*)&sattn[w][(rg + 4 * j) * ASTR + 4 * uc];
        #pragma unroll
        for (int t = 0; t < 4; ++t) {
            int u = 4 * uc + t;
            float4 v0 = sv[w][u * 16 + c2];
            float4 v1 = sv[w][u * 16 + c2 + 8];
            #pragma unroll
            for (int j = 0; j < 4; ++j) {
                float a = (t == 0) ? a4[j].x : (t == 1) ? a4[j].y
                        : (t == 2) ? a4[j].z : a4[j].w;
                acc[j][0].x += a * v0.x; acc[j][0].y += a * v0.y;
                acc[j][0].z += a * v0.z; acc[j][0].w += a * v0.w;
                acc[j][1].x += a * v1.x; acc[j][1].y += a * v1.y;
                acc[j][1].z += a * v1.z; acc[j][1].w += a * v1.w;
            }
        }
    }

    #pragma unroll
    for (int j = 0; j < 4; ++j) {
        int row = rg + 4 * j;
        og[base + row * 16 + c2]     = acc[j][0];
        og[base + row * 16 + c2 + 8] = acc[j][1];
    }
}

extern "C" void kernel_launch(void* const* d_in, const int* in_sizes, int n_in,
                              void* d_out, int out_size) {
    attn_drop_kernel<<<NBLK, TPB>>>(
        (const float4*)d_in[0],   // q
        (const float4*)d_in[1],   // k
        (const float4*)d_in[2],   // v
        (float4*)d_out);
}